// round 1
// baseline (speedup 1.0000x reference)
#include <cuda_runtime.h>
#include <cstdint>

#define OUT_HW   7
#define NBINS    49            // 7*7
#define NSAMP    4             // 2x2 samples per bin
#define CH       256
#define FH       256
#define FW       256
#define HWSZ     (FH*FW)       // 65536
#define CHWSZ    (CH*HWSZ)
#define CPB      64            // channels per block
#define SLOTS    5             // channel slots per block (5*49 = 245 <= 256 threads)

__global__ __launch_bounds__(256, 8)
void rroi_align_kernel(const float* __restrict__ feat,
                       const float* __restrict__ rois,
                       float* __restrict__ out)
{
    const int n     = blockIdx.y;
    const int c0    = blockIdx.x * CPB;
    const int t     = threadIdx.x;
    const int cslot = t / NBINS;         // 0..5 (5 = inactive tail)
    const int bin   = t - cslot * NBINS; // 0..48

    // ---- per-roi parameters (broadcast loads, hit constant-ish L1) ----
    const float* r = rois + n * 6;
    const int   b  = (int)__ldg(r + 0);
    const float cx = __ldg(r + 1) * 0.25f;
    const float cy = __ldg(r + 2) * 0.25f;
    const float rw = fmaxf(__ldg(r + 3) * 0.25f, 0.0f);
    const float rh = fmaxf(__ldg(r + 4) * 0.25f, 0.0f);
    const float th = __ldg(r + 5);

    const float cs = cosf(th);
    const float sn = sinf(th);
    const float bh = rh * (1.0f / OUT_HW);
    const float bw = rw * (1.0f / OUT_HW);

    const int ph = bin / OUT_HW;
    const int pw = bin - ph * OUT_HW;

    // ---- precompute 4 samples: gather offset + premultiplied weights ----
    float w00[NSAMP], w01[NSAMP], w10[NSAMP], w11[NSAMP];
    int   off[NSAMP];
#pragma unroll
    for (int s = 0; s < NSAMP; ++s) {
        const float sy = (s >> 1) ? 0.75f : 0.25f;
        const float sx = (s & 1)  ? 0.75f : 0.25f;
        const float yy = bh * ((float)ph + sy) - rh * 0.5f;
        const float xx = bw * ((float)pw + sx) - rw * 0.5f;
        const float x  = xx * cs + yy * sn + cx;
        const float y  = yy * cs - xx * sn + cy;

        const bool valid = (y > -1.0f) && (y < (float)FH) &&
                           (x > -1.0f) && (x < (float)FW);

        const float ycl = fminf(fmaxf(y, 0.0f), (float)(FH - 1));
        const float xcl = fminf(fmaxf(x, 0.0f), (float)(FW - 1));
        const float y0f = fminf(floorf(ycl), (float)(FH - 2));
        const float x0f = fminf(floorf(xcl), (float)(FW - 2));
        const int   y0  = (int)y0f;
        const int   x0  = (int)x0f;
        const float ly  = ycl - y0f;
        const float lx  = xcl - x0f;
        const float hy  = 1.0f - ly;
        const float hx  = 1.0f - lx;
        const float vf  = valid ? 0.25f : 0.0f;   // premultiply 1/(S*S)

        w00[s] = hy * hx * vf;
        w01[s] = hy * lx * vf;
        w10[s] = ly * hx * vf;
        w11[s] = ly * lx * vf;
        off[s] = y0 * FW + x0;
    }

    if (cslot >= SLOTS) return;  // tail threads only helped warp-uniform math

    const float* fb = feat + (size_t)b * CHWSZ;
    float*       ob = out  + (size_t)n * (CH * NBINS) + bin;

    // ---- channel mainloop: pure gather + FMA (coords live in registers) ----
    for (int c = c0 + cslot; c < c0 + CPB; c += SLOTS) {
        const float* fc = fb + (size_t)c * HWSZ;
        float acc = 0.0f;
#pragma unroll
        for (int s = 0; s < NSAMP; ++s) {
            const float* p = fc + off[s];
            const float v00 = __ldg(p);
            const float v01 = __ldg(p + 1);
            const float v10 = __ldg(p + FW);
            const float v11 = __ldg(p + FW + 1);
            acc += w00[s] * v00 + w01[s] * v01 + w10[s] * v10 + w11[s] * v11;
        }
        ob[(size_t)c * NBINS] = acc;
    }
}

extern "C" void kernel_launch(void* const* d_in, const int* in_sizes, int n_in,
                              void* d_out, int out_size)
{
    const float* feat = (const float*)d_in[0];
    const float* rois = (const float*)d_in[1];
    float*       out  = (float*)d_out;

    const int nrois = in_sizes[1] / 6;   // 1000

    dim3 grid(CH / CPB, nrois);          // (4, 1000)
    dim3 block(256);
    rroi_align_kernel<<<grid, block>>>(feat, rois, out);
}

// round 4
// speedup vs baseline: 1.2728x; 1.2728x over previous
#include <cuda_runtime.h>
#include <cstdint>

#define OUT_HW   7
#define NBINS    49            // 7*7
#define NSAMP    4             // 2x2 samples per bin
#define CH       256
#define FH       256
#define FW       256
#define HWSZ     (FH*FW)       // 65536
#define CHWSZ    (CH*HWSZ)
#define CPB      64            // channels per block
#define SLOTS    5             // channel slots per block (5*49 = 245 <= 256 threads)

// Permutation: rois sorted by (batch, spatial tile) for L2 locality.
__device__ unsigned int g_perm[1024];

__global__ void sort_rois_kernel(const float* __restrict__ rois, int n)
{
    __shared__ unsigned int sk[1024];
    const int t = threadIdx.x;

    unsigned int key;
    if (t < n && n <= 1024) {
        const float* r = rois + t * 6;
        const int   b  = (int)__ldg(r + 0);
        const float cx = __ldg(r + 1) * 0.25f;   // feature-space center
        const float cy = __ldg(r + 2) * 0.25f;
        // 32px feature tiles -> 8x8 grid per image
        int tx = (int)(cx * (1.0f / 32.0f)); tx = min(max(tx, 0), 7);
        int ty = (int)(cy * (1.0f / 32.0f)); ty = min(max(ty, 0), 7);
        const unsigned int k = (unsigned int)(b * 64 + ty * 8 + tx);
        key = (k << 10) | (unsigned int)t;       // stable-ish: idx in low bits
    } else {
        key = 0xFFFFFFFFu;                       // pads sort to the end
    }
    sk[t] = key;
    __syncthreads();

    // Bitonic sort, 1024 elements, ascending
    for (int k = 2; k <= 1024; k <<= 1) {
        for (int j = k >> 1; j > 0; j >>= 1) {
            const int ixj = t ^ j;
            if (ixj > t) {
                const unsigned int a = sk[t];
                const unsigned int c = sk[ixj];
                const bool up = ((t & k) == 0);
                if ((a > c) == up) { sk[t] = c; sk[ixj] = a; }
            }
            __syncthreads();
        }
    }

    if (t < n) {
        g_perm[t] = (n <= 1024) ? (sk[t] & 1023u) : (unsigned int)t;
    }
}

__global__ __launch_bounds__(256, 8)
void rroi_align_kernel(const float* __restrict__ feat,
                       const float* __restrict__ rois,
                       float* __restrict__ out)
{
    const int n     = (int)g_perm[blockIdx.y];   // sorted roi order
    const int c0    = blockIdx.x * CPB;
    const int t     = threadIdx.x;
    const int cslot = t / NBINS;         // 0..5 (5 = inactive tail)
    const int bin   = t - cslot * NBINS; // 0..48

    // ---- per-roi parameters (broadcast loads) ----
    const float* r = rois + n * 6;
    const int   b  = (int)__ldg(r + 0);
    const float cx = __ldg(r + 1) * 0.25f;
    const float cy = __ldg(r + 2) * 0.25f;
    const float rw = fmaxf(__ldg(r + 3) * 0.25f, 0.0f);
    const float rh = fmaxf(__ldg(r + 4) * 0.25f, 0.0f);
    const float th = __ldg(r + 5);

    const float cs = cosf(th);
    const float sn = sinf(th);
    const float bh = rh * (1.0f / OUT_HW);
    const float bw = rw * (1.0f / OUT_HW);

    const int ph = bin / OUT_HW;
    const int pw = bin - ph * OUT_HW;

    // ---- precompute 4 samples: gather offset + premultiplied weights ----
    float w00[NSAMP], w01[NSAMP], w10[NSAMP], w11[NSAMP];
    int   off[NSAMP];
#pragma unroll
    for (int s = 0; s < NSAMP; ++s) {
        const float sy = (s >> 1) ? 0.75f : 0.25f;
        const float sx = (s & 1)  ? 0.75f : 0.25f;
        const float yy = bh * ((float)ph + sy) - rh * 0.5f;
        const float xx = bw * ((float)pw + sx) - rw * 0.5f;
        const float x  = xx * cs + yy * sn + cx;
        const float y  = yy * cs - xx * sn + cy;

        const bool valid = (y > -1.0f) && (y < (float)FH) &&
                           (x > -1.0f) && (x < (float)FW);

        const float ycl = fminf(fmaxf(y, 0.0f), (float)(FH - 1));
        const float xcl = fminf(fmaxf(x, 0.0f), (float)(FW - 1));
        const float y0f = fminf(floorf(ycl), (float)(FH - 2));
        const float x0f = fminf(floorf(xcl), (float)(FW - 2));
        const int   y0  = (int)y0f;
        const int   x0  = (int)x0f;
        const float ly  = ycl - y0f;
        const float lx  = xcl - x0f;
        const float hy  = 1.0f - ly;
        const float hx  = 1.0f - lx;
        const float vf  = valid ? 0.25f : 0.0f;   // premultiply 1/(S*S)

        w00[s] = hy * hx * vf;
        w01[s] = hy * lx * vf;
        w10[s] = ly * hx * vf;
        w11[s] = ly * lx * vf;
        off[s] = y0 * FW + x0;
    }

    if (cslot >= SLOTS) return;  // tail threads only helped warp-uniform math

    const float* fb = feat + (size_t)b * CHWSZ;
    float*       ob = out  + (size_t)n * (CH * NBINS) + bin;

    // ---- channel mainloop: pure gather + FMA (coords live in registers) ----
    for (int c = c0 + cslot; c < c0 + CPB; c += SLOTS) {
        const float* fc = fb + (size_t)c * HWSZ;
        float acc = 0.0f;
#pragma unroll
        for (int s = 0; s < NSAMP; ++s) {
            const float* p = fc + off[s];
            const float v00 = __ldg(p);
            const float v01 = __ldg(p + 1);
            const float v10 = __ldg(p + FW);
            const float v11 = __ldg(p + FW + 1);
            acc += w00[s] * v00 + w01[s] * v01 + w10[s] * v10 + w11[s] * v11;
        }
        ob[(size_t)c * NBINS] = acc;
    }
}

extern "C" void kernel_launch(void* const* d_in, const int* in_sizes, int n_in,
                              void* d_out, int out_size)
{
    const float* feat = (const float*)d_in[0];
    const float* rois = (const float*)d_in[1];
    float*       out  = (float*)d_out;

    const int nrois = in_sizes[1] / 6;   // 1000

    sort_rois_kernel<<<1, 1024>>>(rois, nrois);

    dim3 grid(CH / CPB, nrois);          // (4, 1000)
    dim3 block(256);
    rroi_align_kernel<<<grid, block>>>(feat, rois, out);
}

// round 8
// speedup vs baseline: 1.4138x; 1.1108x over previous
#include <cuda_runtime.h>
#include <cstdint>

#define OUT_HW   7
#define NBINS    49            // 7*7
#define NSAMP    4             // 2x2 samples per bin
#define CH       256
#define FH       256
#define FW       256
#define HWSZ     (FH*FW)       // 65536
#define CHWSZ    (CH*HWSZ)
#define CPB      64            // channels per block
#define SLOTS    5             // channel slots per block (5*49 = 245 <= 256 threads)

// Permutation: rois sorted by (batch, spatial tile) for L2 locality.
__device__ unsigned int g_perm[1024];

__global__ void sort_rois_kernel(const float* __restrict__ rois, int n)
{
    __shared__ unsigned int sk[1024];
    const int t = threadIdx.x;

    unsigned int key;
    if (t < n && n <= 1024) {
        const float* r = rois + t * 6;
        const int   b  = (int)__ldg(r + 0);
        const float cx = __ldg(r + 1) * 0.25f;   // feature-space center
        const float cy = __ldg(r + 2) * 0.25f;
        // 32px feature tiles -> 8x8 grid per image
        int tx = (int)(cx * (1.0f / 32.0f)); tx = min(max(tx, 0), 7);
        int ty = (int)(cy * (1.0f / 32.0f)); ty = min(max(ty, 0), 7);
        const unsigned int k = (unsigned int)(b * 64 + ty * 8 + tx);
        key = (k << 10) | (unsigned int)t;       // stable-ish: idx in low bits
    } else {
        key = 0xFFFFFFFFu;                       // pads sort to the end
    }
    sk[t] = key;
    __syncthreads();

    // Bitonic sort, 1024 elements, ascending
    for (int k = 2; k <= 1024; k <<= 1) {
        for (int j = k >> 1; j > 0; j >>= 1) {
            const int ixj = t ^ j;
            if (ixj > t) {
                const unsigned int a = sk[t];
                const unsigned int c = sk[ixj];
                const bool up = ((t & k) == 0);
                if ((a > c) == up) { sk[t] = c; sk[ixj] = a; }
            }
            __syncthreads();
        }
    }

    if (t < n) {
        g_perm[t] = (n <= 1024) ? (sk[t] & 1023u) : (unsigned int)t;
    }
}

__global__ __launch_bounds__(256, 5)
void rroi_align_kernel(const float* __restrict__ feat,
                       const float* __restrict__ rois,
                       float* __restrict__ out)
{
    const int n     = (int)g_perm[blockIdx.y];   // sorted roi order
    const int c0    = blockIdx.x * CPB;
    const int t     = threadIdx.x;
    const int cslot = t / NBINS;         // 0..5 (5 = inactive tail)
    const int bin   = t - cslot * NBINS; // 0..48

    // ---- per-roi parameters (broadcast loads) ----
    const float* r = rois + n * 6;
    const int   b  = (int)__ldg(r + 0);
    const float cx = __ldg(r + 1) * 0.25f;
    const float cy = __ldg(r + 2) * 0.25f;
    const float rw = fmaxf(__ldg(r + 3) * 0.25f, 0.0f);
    const float rh = fmaxf(__ldg(r + 4) * 0.25f, 0.0f);
    const float th = __ldg(r + 5);

    const float cs = cosf(th);
    const float sn = sinf(th);
    const float bh = rh * (1.0f / OUT_HW);
    const float bw = rw * (1.0f / OUT_HW);

    const int ph = bin / OUT_HW;
    const int pw = bin - ph * OUT_HW;

    // ---- precompute 4 samples: gather offset + premultiplied weights ----
    float w00[NSAMP], w01[NSAMP], w10[NSAMP], w11[NSAMP];
    int   off[NSAMP];
#pragma unroll
    for (int s = 0; s < NSAMP; ++s) {
        const float sy = (s >> 1) ? 0.75f : 0.25f;
        const float sx = (s & 1)  ? 0.75f : 0.25f;
        const float yy = bh * ((float)ph + sy) - rh * 0.5f;
        const float xx = bw * ((float)pw + sx) - rw * 0.5f;
        const float x  = xx * cs + yy * sn + cx;
        const float y  = yy * cs - xx * sn + cy;

        const bool valid = (y > -1.0f) && (y < (float)FH) &&
                           (x > -1.0f) && (x < (float)FW);

        const float ycl = fminf(fmaxf(y, 0.0f), (float)(FH - 1));
        const float xcl = fminf(fmaxf(x, 0.0f), (float)(FW - 1));
        const float y0f = fminf(floorf(ycl), (float)(FH - 2));
        const float x0f = fminf(floorf(xcl), (float)(FW - 2));
        const int   y0  = (int)y0f;
        const int   x0  = (int)x0f;
        const float ly  = ycl - y0f;
        const float lx  = xcl - x0f;
        const float hy  = 1.0f - ly;
        const float hx  = 1.0f - lx;
        const float vf  = valid ? 0.25f : 0.0f;   // premultiply 1/(S*S)

        w00[s] = hy * hx * vf;
        w01[s] = hy * lx * vf;
        w10[s] = ly * hx * vf;
        w11[s] = ly * lx * vf;
        off[s] = y0 * FW + x0;
    }

    if (cslot >= SLOTS) return;  // tail threads only helped warp-uniform math

    const float* fb = feat + (size_t)b * CHWSZ;
    float*       ob = out  + (size_t)n * (CH * NBINS) + bin;

    // ---- channel mainloop: 2 channels per iteration for 32-deep MLP ----
    int c = c0 + cslot;
    const int cend = c0 + CPB;
    for (; c + SLOTS < cend; c += 2 * SLOTS) {
        const float* fcA = fb + (size_t)c * HWSZ;
        const float* fcB = fcA + (size_t)SLOTS * HWSZ;
        float accA = 0.0f, accB = 0.0f;

        // batch all 32 loads (independent), then FMAs
        float a00[NSAMP], a01[NSAMP], a10[NSAMP], a11[NSAMP];
        float b00[NSAMP], b01[NSAMP], b10[NSAMP], b11[NSAMP];
#pragma unroll
        for (int s = 0; s < NSAMP; ++s) {
            const float* pA = fcA + off[s];
            const float* pB = fcB + off[s];
            a00[s] = __ldg(pA);
            a01[s] = __ldg(pA + 1);
            a10[s] = __ldg(pA + FW);
            a11[s] = __ldg(pA + FW + 1);
            b00[s] = __ldg(pB);
            b01[s] = __ldg(pB + 1);
            b10[s] = __ldg(pB + FW);
            b11[s] = __ldg(pB + FW + 1);
        }
#pragma unroll
        for (int s = 0; s < NSAMP; ++s) {
            accA += w00[s] * a00[s] + w01[s] * a01[s] + w10[s] * a10[s] + w11[s] * a11[s];
            accB += w00[s] * b00[s] + w01[s] * b01[s] + w10[s] * b10[s] + w11[s] * b11[s];
        }
        ob[(size_t)c * NBINS] = accA;
        ob[(size_t)(c + SLOTS) * NBINS] = accB;
    }
    // remainder channel (threads with 13 channels)
    if (c < cend) {
        const float* fc = fb + (size_t)c * HWSZ;
        float acc = 0.0f;
#pragma unroll
        for (int s = 0; s < NSAMP; ++s) {
            const float* p = fc + off[s];
            acc += w00[s] * __ldg(p)      + w01[s] * __ldg(p + 1)
                 + w10[s] * __ldg(p + FW) + w11[s] * __ldg(p + FW + 1);
        }
        ob[(size_t)c * NBINS] = acc;
    }
}

extern "C" void kernel_launch(void* const* d_in, const int* in_sizes, int n_in,
                              void* d_out, int out_size)
{
    const float* feat = (const float*)d_in[0];
    const float* rois = (const float*)d_in[1];
    float*       out  = (float*)d_out;

    const int nrois = in_sizes[1] / 6;   // 1000

    sort_rois_kernel<<<1, 1024>>>(rois, nrois);

    dim3 grid(CH / CPB, nrois);          // (4, 1000)
    dim3 block(256);
    rroi_align_kernel<<<grid, block>>>(feat, rois, out);
}